// round 10
// baseline (speedup 1.0000x reference)
#include <cuda_runtime.h>
#include <cuda_fp16.h>
#include <math.h>

constexpr int BB = 2;
constexpr int NN = 2048;
constexpr int CC = 1024;
constexpr int HH = 8;
constexpr int DH = 128;
constexpr int MALL = BB * NN;  // 4096

__device__ __half g_xqh[(size_t)MALL * CC];
__device__ __half g_xkvh[(size_t)MALL * CC];
__device__ __half g_qh[(size_t)MALL * CC];
__device__ __half g_kh[(size_t)MALL * CC];
__device__ __half g_vh[(size_t)MALL * CC];
__device__ __half g_atth[(size_t)MALL * CC];
__device__ __half g_wt[4ull * CC * CC];  // W^T fp16, [4][n][k]

// ---------------------------------------------------------------------------
// helpers
// ---------------------------------------------------------------------------
__device__ __forceinline__ unsigned h2u(__half2 h) {
  return *reinterpret_cast<unsigned*>(&h);
}

__device__ __forceinline__ void hmma16(float* c, const unsigned* a, unsigned b0,
                                       unsigned b1) {
  asm volatile(
      "mma.sync.aligned.m16n8k16.row.col.f32.f16.f16.f32 "
      "{%0,%1,%2,%3}, {%4,%5,%6,%7}, {%8,%9}, {%0,%1,%2,%3};"
      : "+f"(c[0]), "+f"(c[1]), "+f"(c[2]), "+f"(c[3])
      : "r"(a[0]), "r"(a[1]), "r"(a[2]), "r"(a[3]), "r"(b0), "r"(b1));
}

__device__ __forceinline__ void ldsm_x4(unsigned* r, unsigned addr) {
  asm volatile(
      "ldmatrix.sync.aligned.m8n8.x4.shared.b16 {%0,%1,%2,%3}, [%4];"
      : "=r"(r[0]), "=r"(r[1]), "=r"(r[2]), "=r"(r[3])
      : "r"(addr));
}
__device__ __forceinline__ void ldsm_x4t(unsigned* r, unsigned addr) {
  asm volatile(
      "ldmatrix.sync.aligned.m8n8.x4.trans.shared.b16 {%0,%1,%2,%3}, [%4];"
      : "=r"(r[0]), "=r"(r[1]), "=r"(r[2]), "=r"(r[3])
      : "r"(addr));
}

#define CP_ASYNC16(dst, src)                                           \
  asm volatile("cp.async.cg.shared.global [%0], [%1], 16;" ::"r"(dst), \
               "l"(src))
#define CP_COMMIT() asm volatile("cp.async.commit_group;")
#define CP_WAIT1() asm volatile("cp.async.wait_group 1;")

__device__ __forceinline__ void store2(float* p, float x, float y) {
  *(float2*)p = make_float2(x, y);
}
__device__ __forceinline__ void store2(__half* p, float x, float y) {
  *(__half2*)p = __floats2half2_rn(x, y);
}

// ---------------------------------------------------------------------------
// fp32 -> fp16 convert
// ---------------------------------------------------------------------------
__global__ __launch_bounds__(256) void f2h_kernel(const float* __restrict__ in,
                                                  __half* __restrict__ out) {
  const int i = blockIdx.x * 256 + threadIdx.x;
  float4 v = ((const float4*)in)[i];
  ((__half2*)out)[2 * i] = __floats2half2_rn(v.x, v.y);
  ((__half2*)out)[2 * i + 1] = __floats2half2_rn(v.z, v.w);
}

// ---------------------------------------------------------------------------
// Transpose + fp16 convert: Wt[z][n][k] = (half)W_z[k][n]
// ---------------------------------------------------------------------------
__global__ __launch_bounds__(256) void transpose_h_kernel(
    const float* __restrict__ W0, const float* __restrict__ W1,
    const float* __restrict__ W2, const float* __restrict__ W3,
    __half* __restrict__ out) {
  __shared__ float tile[32][33];
  const float* W = (blockIdx.z == 0) ? W0
                   : (blockIdx.z == 1) ? W1
                   : (blockIdx.z == 2) ? W2 : W3;
  __half* o = out + (size_t)blockIdx.z * CC * CC;
  const int k0 = blockIdx.y * 32, n0 = blockIdx.x * 32;
  const int tx = threadIdx.x & 31, ty = threadIdx.x >> 5;
#pragma unroll
  for (int i = 0; i < 32; i += 8)
    tile[ty + i][tx] = W[(size_t)(k0 + ty + i) * CC + n0 + tx];
  __syncthreads();
#pragma unroll
  for (int i = 0; i < 32; i += 8)
    o[(size_t)(n0 + ty + i) * CC + k0 + tx] = __float2half(tile[tx][ty + i]);
}

// ---------------------------------------------------------------------------
// fp16 GEMM with cp.async 3-stage pipeline + ldmatrix fragments (the ONE
// change vs round 9's verified 42.8us kernel).
// ---------------------------------------------------------------------------
constexpr int GST2 = 20;                 // half2 words per row
constexpr int GTILE = 128 * GST2;        // half2 words per tile
constexpr int GTILE_B = GTILE * 4;       // bytes
constexpr int GSTAGES = 3;
constexpr int GEMM_SMEM = GSTAGES * GTILE_B * 2;  // 61,440 B

template <typename OutT>
__global__ __launch_bounds__(256) void hgemm_cp_kernel(
    const __half* __restrict__ A, const __half* __restrict__ Bt,
    const float* __restrict__ bias, OutT* __restrict__ C) {
  constexpr int K = 1024, N = 1024;
  extern __shared__ __half2 dsm[];
  __half2* sA = dsm;
  __half2* sB = dsm + GSTAGES * GTILE;

  const int tid = threadIdx.x;
  const int warp = tid >> 5, lane = tid & 31;
  const int g = lane >> 2, t = lane & 3;
  const int wm = warp & 3, wn = warp >> 2;
  const int bx = blockIdx.x, by = blockIdx.y;

  const int cr = tid >> 1;       // copy row 0..127
  const int cw = (tid & 1) * 2;  // uint4 index {0,2}

  const __half* Ab = A + (size_t)(by * 128 + cr) * K + cw * 8;
  const __half* Bb = Bt + (size_t)(bx * 128 + cr) * K + cw * 8;

  const unsigned sa0 =
      (unsigned)__cvta_generic_to_shared(sA) + cr * (GST2 * 4) + cw * 16;
  const unsigned sb0 =
      (unsigned)__cvta_generic_to_shared(sB) + cr * (GST2 * 4) + cw * 16;

  // ldmatrix lane addressing
  const int lrow = lane & 15, l16 = lane >> 4;
  const int bcol = (lane & 7) + 8 * ((lane >> 3) & 1);
  const unsigned aBase = (unsigned)__cvta_generic_to_shared(sA) +
                         (wm * 32 + lrow) * (GST2 * 4) + l16 * 16;
  const unsigned bBase = (unsigned)__cvta_generic_to_shared(sB) +
                         (wn * 64 + bcol) * (GST2 * 4) + l16 * 16;

  float acc[2][8][4];
#pragma unroll
  for (int mt = 0; mt < 2; mt++)
#pragma unroll
    for (int nt = 0; nt < 8; nt++)
#pragma unroll
      for (int i = 0; i < 4; i++) acc[mt][nt][i] = 0.f;

  auto issue = [&](int stage, int k0) {
    const unsigned da = sa0 + stage * GTILE_B;
    const unsigned db = sb0 + stage * GTILE_B;
    CP_ASYNC16(da, Ab + k0);
    CP_ASYNC16(da + 16, Ab + k0 + 8);
    CP_ASYNC16(db, Bb + k0);
    CP_ASYNC16(db + 16, Bb + k0 + 8);
    CP_COMMIT();
  };

  issue(0, 0);
  issue(1, 32);

  for (int it = 0; it < K / 32; it++) {
    CP_WAIT1();
    __syncthreads();
    const int st = it % GSTAGES;
    const unsigned aS = aBase + st * GTILE_B;
    const unsigned bS = bBase + st * GTILE_B;

#pragma unroll
    for (int ks = 0; ks < 2; ks++) {
      unsigned a0[4], a1[4];
      ldsm_x4(a0, aS + ks * 32);
      ldsm_x4(a1, aS + 16 * (GST2 * 4) + ks * 32);
#pragma unroll
      for (int j = 0; j < 4; j++) {
        unsigned bb[4];
        ldsm_x4(bb, bS + j * (16 * GST2 * 4) + ks * 32);
        hmma16(acc[0][2 * j], a0, bb[0], bb[2]);
        hmma16(acc[1][2 * j], a1, bb[0], bb[2]);
        hmma16(acc[0][2 * j + 1], a0, bb[1], bb[3]);
        hmma16(acc[1][2 * j + 1], a1, bb[1], bb[3]);
      }
    }
    if (it + 2 < K / 32) issue((it + 2) % GSTAGES, (it + 2) * 32);
    __syncthreads();
  }

#pragma unroll
  for (int mt = 0; mt < 2; mt++) {
    const int r0 = by * 128 + wm * 32 + mt * 16 + g;
#pragma unroll
    for (int nt = 0; nt < 8; nt++) {
      const int c = bx * 128 + wn * 64 + nt * 8 + 2 * t;
      const float bx0 = bias[c], bx1 = bias[c + 1];
      store2(C + (size_t)r0 * N + c, acc[mt][nt][0] + bx0,
             acc[mt][nt][1] + bx1);
      store2(C + (size_t)(r0 + 8) * N + c, acc[mt][nt][2] + bx0,
             acc[mt][nt][3] + bx1);
    }
  }
}

// ---------------------------------------------------------------------------
// Flash attention (round-9 verified: uint4 loads, single K/V buffer, two
// barriers, ldmatrix fragments). UNCHANGED.
// ---------------------------------------------------------------------------
constexpr int Q2_STR = 68;
constexpr int V_STR = 136;  // halves per row (272B, 16B-aligned)
constexpr int OK2 = 128 * Q2_STR;
constexpr int OV2 = OK2 + 64 * Q2_STR;
constexpr int ATT_SMEM_BYTES = (OV2 + 64 * V_STR / 2) * 4;  // 69,632 B

__global__ __launch_bounds__(256) void attn_fp16_kernel(
    const __half* __restrict__ Q, const __half* __restrict__ K,
    const __half* __restrict__ V, __half* __restrict__ O) {
  extern __shared__ __half2 sm2[];
  __half* sVh = reinterpret_cast<__half*>(sm2 + OV2);

  const int tid = threadIdx.x;
  const int warp = tid >> 5, lane = tid & 31;
  const int g = lane >> 2, t = lane & 3;
  const int rr = warp * 16;
  const int bh = blockIdx.y;
  const int b = bh >> 3, h = bh & 7;
  const int n0 = blockIdx.x * 128;

  const __half* Qb = Q + (size_t)b * NN * CC + (size_t)h * DH;
  const __half* Kb = K + (size_t)b * NN * CC + (size_t)h * DH;
  const __half* Vb = V + (size_t)b * NN * CC + (size_t)h * DH;
  const float scale = 0.08838834764831845f;

  const unsigned smb = (unsigned)__cvta_generic_to_shared(sm2);

  const int lrow = lane & 15, l16 = lane >> 4;
  const int bcol = (lane & 7) + 8 * ((lane >> 3) & 1);
  const unsigned qlm = smb + (rr + lrow) * (Q2_STR * 4) + l16 * 16;
  const unsigned klm = smb + OK2 * 4 + bcol * (Q2_STR * 4) + l16 * 16;
  const unsigned vlm = smb + OV2 * 4 + bcol * (V_STR * 2) + l16 * 16;

#pragma unroll
  for (int i = 0; i < 8; i++) {
    int l = tid + 256 * i;
    int r = l >> 4, w = l & 15;
    *(uint4*)(sm2 + r * Q2_STR + w * 4) =
        *(const uint4*)(Qb + (size_t)(n0 + r) * CC + w * 8);
  }

  float m0 = -INFINITY, m1 = -INFINITY, l0 = 0.f, l1 = 0.f;
  float oacc[16][4];
#pragma unroll
  for (int nt = 0; nt < 16; nt++)
#pragma unroll
    for (int i = 0; i < 4; i++) oacc[nt][i] = 0.f;
  __syncthreads();

  for (int j0 = 0; j0 < NN; j0 += 64) {
#pragma unroll
    for (int i = 0; i < 4; i++) {
      int l = tid + 256 * i;
      int r = l >> 4, w = l & 15;
      *(uint4*)(sm2 + OK2 + r * Q2_STR + w * 4) =
          *(const uint4*)(Kb + (size_t)(j0 + r) * CC + w * 8);
      *(uint4*)(sVh + r * V_STR + w * 8) =
          *(const uint4*)(Vb + (size_t)(j0 + r) * CC + w * 8);
    }
    __syncthreads();

    float sacc[8][4];
#pragma unroll
    for (int nt = 0; nt < 8; nt++)
#pragma unroll
      for (int i = 0; i < 4; i++) sacc[nt][i] = 0.f;

#pragma unroll
    for (int ks = 0; ks < 8; ks++) {
      unsigned a[4];
      ldsm_x4(a, qlm + ks * 32);
#pragma unroll
      for (int j = 0; j < 4; j++) {
        unsigned bb[4];
        ldsm_x4(bb, klm + j * (16 * Q2_STR * 4) + ks * 32);
        hmma16(sacc[2 * j], a, bb[0], bb[2]);
        hmma16(sacc[2 * j + 1], a, bb[1], bb[3]);
      }
    }
#pragma unroll
    for (int nt = 0; nt < 8; nt++)
#pragma unroll
      for (int i = 0; i < 4; i++) sacc[nt][i] *= scale;

    float mx0 = -INFINITY, mx1 = -INFINITY;
#pragma unroll
    for (int nt = 0; nt < 8; nt++) {
      mx0 = fmaxf(mx0, fmaxf(sacc[nt][0], sacc[nt][1]));
      mx1 = fmaxf(mx1, fmaxf(sacc[nt][2], sacc[nt][3]));
    }
    mx0 = fmaxf(mx0, __shfl_xor_sync(0xffffffffu, mx0, 1));
    mx0 = fmaxf(mx0, __shfl_xor_sync(0xffffffffu, mx0, 2));
    mx1 = fmaxf(mx1, __shfl_xor_sync(0xffffffffu, mx1, 1));
    mx1 = fmaxf(mx1, __shfl_xor_sync(0xffffffffu, mx1, 2));

    const float mn0 = fmaxf(m0, mx0), mn1 = fmaxf(m1, mx1);
    const float al0 = __expf(m0 - mn0), al1 = __expf(m1 - mn1);
    m0 = mn0;
    m1 = mn1;

    __half2 pa[8], pb[8];
    float s0 = 0.f, s1 = 0.f;
#pragma unroll
    for (int nt = 0; nt < 8; nt++) {
      pa[nt] = __floats2half2_rn(__expf(sacc[nt][0] - mn0),
                                 __expf(sacc[nt][1] - mn0));
      pb[nt] = __floats2half2_rn(__expf(sacc[nt][2] - mn1),
                                 __expf(sacc[nt][3] - mn1));
      float2 fa = __half22float2(pa[nt]);
      float2 fb = __half22float2(pb[nt]);
      s0 += fa.x + fa.y;  // L from rounded P -> matches PV numerator
      s1 += fb.x + fb.y;
    }
    s0 += __shfl_xor_sync(0xffffffffu, s0, 1);
    s0 += __shfl_xor_sync(0xffffffffu, s0, 2);
    s1 += __shfl_xor_sync(0xffffffffu, s1, 1);
    s1 += __shfl_xor_sync(0xffffffffu, s1, 2);
    l0 = l0 * al0 + s0;
    l1 = l1 * al1 + s1;

#pragma unroll
    for (int nt = 0; nt < 16; nt++) {
      oacc[nt][0] *= al0;
      oacc[nt][1] *= al0;
      oacc[nt][2] *= al1;
      oacc[nt][3] *= al1;
    }

#pragma unroll
    for (int ks = 0; ks < 4; ks++) {
      unsigned a[4];
      a[0] = h2u(pa[2 * ks]);
      a[1] = h2u(pb[2 * ks]);
      a[2] = h2u(pa[2 * ks + 1]);
      a[3] = h2u(pb[2 * ks + 1]);
      const unsigned vK = vlm + ks * (16 * V_STR * 2);
#pragma unroll
      for (int j = 0; j < 8; j++) {
        unsigned bb[4];
        ldsm_x4t(bb, vK + j * 32);
        hmma16(oacc[2 * j], a, bb[0], bb[1]);
        hmma16(oacc[2 * j + 1], a, bb[2], bb[3]);
      }
    }
    __syncthreads();
  }

  __half* Ob = O + (size_t)b * NN * CC + (size_t)h * DH;
  const float inv0 = 1.0f / l0, inv1 = 1.0f / l1;
  const int row = n0 + rr + g;
#pragma unroll
  for (int nt = 0; nt < 16; nt++) {
    const int c = nt * 8 + 2 * t;
    *(__half2*)(Ob + (size_t)row * CC + c) =
        __floats2half2_rn(oacc[nt][0] * inv0, oacc[nt][1] * inv0);
    *(__half2*)(Ob + (size_t)(row + 8) * CC + c) =
        __floats2half2_rn(oacc[nt][2] * inv1, oacc[nt][3] * inv1);
  }
}

// ---------------------------------------------------------------------------
extern "C" void kernel_launch(void* const* d_in, const int* in_sizes, int n_in,
                              void* d_out, int out_size) {
  const float* xq = (const float*)d_in[0];
  const float* xkv = (const float*)d_in[1];
  const float* Wq = (const float*)d_in[2];
  const float* bq = (const float*)d_in[3];
  const float* Wk = (const float*)d_in[4];
  const float* bk = (const float*)d_in[5];
  const float* Wv = (const float*)d_in[6];
  const float* bv = (const float*)d_in[7];
  const float* Wo = (const float*)d_in[8];
  const float* bo = (const float*)d_in[9];
  float* out = (float*)d_out;

  __half *xqh, *xkvh, *qh, *kh, *vh, *atth, *wt;
  cudaGetSymbolAddress((void**)&xqh, g_xqh);
  cudaGetSymbolAddress((void**)&xkvh, g_xkvh);
  cudaGetSymbolAddress((void**)&qh, g_qh);
  cudaGetSymbolAddress((void**)&kh, g_kh);
  cudaGetSymbolAddress((void**)&vh, g_vh);
  cudaGetSymbolAddress((void**)&atth, g_atth);
  cudaGetSymbolAddress((void**)&wt, g_wt);

  cudaFuncSetAttribute(attn_fp16_kernel,
                       cudaFuncAttributeMaxDynamicSharedMemorySize,
                       ATT_SMEM_BYTES);
  cudaFuncSetAttribute(hgemm_cp_kernel<__half>,
                       cudaFuncAttributeMaxDynamicSharedMemorySize, GEMM_SMEM);
  cudaFuncSetAttribute(hgemm_cp_kernel<float>,
                       cudaFuncAttributeMaxDynamicSharedMemorySize, GEMM_SMEM);

  const size_t WSZ = (size_t)CC * CC;
  const int CV_BLK = (MALL * CC / 4) / 256;
  f2h_kernel<<<CV_BLK, 256>>>(xq, xqh);
  f2h_kernel<<<CV_BLK, 256>>>(xkv, xkvh);
  transpose_h_kernel<<<dim3(32, 32, 4), 256>>>(Wq, Wk, Wv, Wo, wt);

  dim3 gg(CC / 128, MALL / 128);  // (8, 32)
  hgemm_cp_kernel<__half><<<gg, 256, GEMM_SMEM>>>(xqh, wt + 0 * WSZ, bq, qh);
  hgemm_cp_kernel<__half><<<gg, 256, GEMM_SMEM>>>(xkvh, wt + 1 * WSZ, bk, kh);
  hgemm_cp_kernel<__half><<<gg, 256, GEMM_SMEM>>>(xkvh, wt + 2 * WSZ, bv, vh);
  attn_fp16_kernel<<<dim3(NN / 128, BB * HH), 256, ATT_SMEM_BYTES>>>(qh, kh,
                                                                     vh, atth);
  hgemm_cp_kernel<float><<<gg, 256, GEMM_SMEM>>>(atth, wt + 3 * WSZ, bo, out);
}

// round 13
// speedup vs baseline: 1.0354x; 1.0354x over previous
#include <cuda_runtime.h>
#include <cuda_fp16.h>
#include <math.h>

constexpr int BB = 2;
constexpr int NN = 2048;
constexpr int CC = 1024;
constexpr int HH = 8;
constexpr int DH = 128;
constexpr int MALL = BB * NN;  // 4096

__device__ __half g_xqh[(size_t)MALL * CC];
__device__ __half g_xkvh[(size_t)MALL * CC];
__device__ __half g_qh[(size_t)MALL * CC];
__device__ __half g_kh[(size_t)MALL * CC];
__device__ __half g_vh[(size_t)MALL * CC];
__device__ __half g_atth[(size_t)MALL * CC];
__device__ __half g_wt[4ull * CC * CC];  // W^T fp16, [4][n][k]

// ---------------------------------------------------------------------------
// helpers
// ---------------------------------------------------------------------------
__device__ __forceinline__ unsigned h2u(__half2 h) {
  return *reinterpret_cast<unsigned*>(&h);
}

__device__ __forceinline__ void hmma16(float* c, const unsigned* a, unsigned b0,
                                       unsigned b1) {
  asm volatile(
      "mma.sync.aligned.m16n8k16.row.col.f32.f16.f16.f32 "
      "{%0,%1,%2,%3}, {%4,%5,%6,%7}, {%8,%9}, {%0,%1,%2,%3};"
      : "+f"(c[0]), "+f"(c[1]), "+f"(c[2]), "+f"(c[3])
      : "r"(a[0]), "r"(a[1]), "r"(a[2]), "r"(a[3]), "r"(b0), "r"(b1));
}

__device__ __forceinline__ void ldsm_x4(unsigned* r, unsigned addr) {
  asm volatile(
      "ldmatrix.sync.aligned.m8n8.x4.shared.b16 {%0,%1,%2,%3}, [%4];"
      : "=r"(r[0]), "=r"(r[1]), "=r"(r[2]), "=r"(r[3])
      : "r"(addr));
}
__device__ __forceinline__ void ldsm_x4t(unsigned* r, unsigned addr) {
  asm volatile(
      "ldmatrix.sync.aligned.m8n8.x4.trans.shared.b16 {%0,%1,%2,%3}, [%4];"
      : "=r"(r[0]), "=r"(r[1]), "=r"(r[2]), "=r"(r[3])
      : "r"(addr));
}

#define CP_ASYNC16(dst, src)                                           \
  asm volatile("cp.async.cg.shared.global [%0], [%1], 16;" ::"r"(dst), \
               "l"(src))
#define CP_COMMIT() asm volatile("cp.async.commit_group;")
#define CP_WAIT1() asm volatile("cp.async.wait_group 1;")

__device__ __forceinline__ void store2(float* p, float x, float y) {
  *(float2*)p = make_float2(x, y);
}
__device__ __forceinline__ void store2(__half* p, float x, float y) {
  *(__half2*)p = __floats2half2_rn(x, y);
}

// ---------------------------------------------------------------------------
// fp32 -> fp16 convert
// ---------------------------------------------------------------------------
__global__ __launch_bounds__(256) void f2h_kernel(const float* __restrict__ in,
                                                  __half* __restrict__ out) {
  const int i = blockIdx.x * 256 + threadIdx.x;
  float4 v = ((const float4*)in)[i];
  ((__half2*)out)[2 * i] = __floats2half2_rn(v.x, v.y);
  ((__half2*)out)[2 * i + 1] = __floats2half2_rn(v.z, v.w);
}

// ---------------------------------------------------------------------------
// Transpose + fp16 convert: Wt[z][n][k] = (half)W_z[k][n]
// ---------------------------------------------------------------------------
__global__ __launch_bounds__(256) void transpose_h_kernel(
    const float* __restrict__ W0, const float* __restrict__ W1,
    const float* __restrict__ W2, const float* __restrict__ W3,
    __half* __restrict__ out) {
  __shared__ float tile[32][33];
  const float* W = (blockIdx.z == 0) ? W0
                   : (blockIdx.z == 1) ? W1
                   : (blockIdx.z == 2) ? W2 : W3;
  __half* o = out + (size_t)blockIdx.z * CC * CC;
  const int k0 = blockIdx.y * 32, n0 = blockIdx.x * 32;
  const int tx = threadIdx.x & 31, ty = threadIdx.x >> 5;
#pragma unroll
  for (int i = 0; i < 32; i += 8)
    tile[ty + i][tx] = W[(size_t)(k0 + ty + i) * CC + n0 + tx];
  __syncthreads();
#pragma unroll
  for (int i = 0; i < 32; i += 8)
    o[(size_t)(n0 + ty + i) * CC + k0 + tx] = __float2half(tile[tx][ty + i]);
}

// ---------------------------------------------------------------------------
// fp16 GEMM with cp.async 3-stage pipeline + ldmatrix (round-10 verified).
// ---------------------------------------------------------------------------
constexpr int GST2 = 20;                 // half2 words per row
constexpr int GTILE = 128 * GST2;        // half2 words per tile
constexpr int GTILE_B = GTILE * 4;       // bytes
constexpr int GSTAGES = 3;
constexpr int GEMM_SMEM = GSTAGES * GTILE_B * 2;  // 61,440 B

template <typename OutT>
__global__ __launch_bounds__(256) void hgemm_cp_kernel(
    const __half* __restrict__ A, const __half* __restrict__ Bt,
    const float* __restrict__ bias, OutT* __restrict__ C) {
  constexpr int K = 1024, N = 1024;
  extern __shared__ __half2 dsm[];
  __half2* sA = dsm;
  __half2* sB = dsm + GSTAGES * GTILE;

  const int tid = threadIdx.x;
  const int warp = tid >> 5, lane = tid & 31;
  const int g = lane >> 2, t = lane & 3;
  const int wm = warp & 3, wn = warp >> 2;
  const int bx = blockIdx.x, by = blockIdx.y;

  const int cr = tid >> 1;       // copy row 0..127
  const int cw = (tid & 1) * 2;  // uint4 index {0,2}

  const __half* Ab = A + (size_t)(by * 128 + cr) * K + cw * 8;
  const __half* Bb = Bt + (size_t)(bx * 128 + cr) * K + cw * 8;

  const unsigned sa0 =
      (unsigned)__cvta_generic_to_shared(sA) + cr * (GST2 * 4) + cw * 16;
  const unsigned sb0 =
      (unsigned)__cvta_generic_to_shared(sB) + cr * (GST2 * 4) + cw * 16;

  const int lrow = lane & 15, l16 = lane >> 4;
  const int bcol = (lane & 7) + 8 * ((lane >> 3) & 1);
  const unsigned aBase = (unsigned)__cvta_generic_to_shared(sA) +
                         (wm * 32 + lrow) * (GST2 * 4) + l16 * 16;
  const unsigned bBase = (unsigned)__cvta_generic_to_shared(sB) +
                         (wn * 64 + bcol) * (GST2 * 4) + l16 * 16;

  float acc[2][8][4];
#pragma unroll
  for (int mt = 0; mt < 2; mt++)
#pragma unroll
    for (int nt = 0; nt < 8; nt++)
#pragma unroll
      for (int i = 0; i < 4; i++) acc[mt][nt][i] = 0.f;

  auto issue = [&](int stage, int k0) {
    const unsigned da = sa0 + stage * GTILE_B;
    const unsigned db = sb0 + stage * GTILE_B;
    CP_ASYNC16(da, Ab + k0);
    CP_ASYNC16(da + 16, Ab + k0 + 8);
    CP_ASYNC16(db, Bb + k0);
    CP_ASYNC16(db + 16, Bb + k0 + 8);
    CP_COMMIT();
  };

  issue(0, 0);
  issue(1, 32);

  for (int it = 0; it < K / 32; it++) {
    CP_WAIT1();
    __syncthreads();
    const int st = it % GSTAGES;
    const unsigned aS = aBase + st * GTILE_B;
    const unsigned bS = bBase + st * GTILE_B;

#pragma unroll
    for (int ks = 0; ks < 2; ks++) {
      unsigned a0[4], a1[4];
      ldsm_x4(a0, aS + ks * 32);
      ldsm_x4(a1, aS + 16 * (GST2 * 4) + ks * 32);
#pragma unroll
      for (int j = 0; j < 4; j++) {
        unsigned bb[4];
        ldsm_x4(bb, bS + j * (16 * GST2 * 4) + ks * 32);
        hmma16(acc[0][2 * j], a0, bb[0], bb[2]);
        hmma16(acc[1][2 * j], a1, bb[0], bb[2]);
        hmma16(acc[0][2 * j + 1], a0, bb[1], bb[3]);
        hmma16(acc[1][2 * j + 1], a1, bb[1], bb[3]);
      }
    }
    if (it + 2 < K / 32) issue((it + 2) % GSTAGES, (it + 2) * 32);
    __syncthreads();
  }

#pragma unroll
  for (int mt = 0; mt < 2; mt++) {
    const int r0 = by * 128 + wm * 32 + mt * 16 + g;
#pragma unroll
    for (int nt = 0; nt < 8; nt++) {
      const int c = bx * 128 + wn * 64 + nt * 8 + 2 * t;
      const float bx0 = bias[c], bx1 = bias[c + 1];
      store2(C + (size_t)r0 * N + c, acc[mt][nt][0] + bx0,
             acc[mt][nt][1] + bx1);
      store2(C + (size_t)(r0 + 8) * N + c, acc[mt][nt][2] + bx0,
             acc[mt][nt][3] + bx1);
    }
  }
}

// ---------------------------------------------------------------------------
// Flash attention, Br=64 / 128 threads / 4 warps, 2 CTAs per SM.
// Warp-level code identical to round-9's verified kernel; only tile height,
// loop bounds, offsets, grid change. Q pre-scaled at smem load.
// smem: sQ[64][68]h2, sK[64][68]h2, sV half[64][136]  (52,224 B)
// ---------------------------------------------------------------------------
constexpr int Q2_STR = 68;
constexpr int V_STR = 136;
constexpr int OK2 = 64 * Q2_STR;           // 4352
constexpr int OV2 = OK2 + 64 * Q2_STR;     // 8704
constexpr int ATT_SMEM_BYTES = (OV2 + 64 * V_STR / 2) * 4;  // 52,224 B

__global__ __launch_bounds__(128, 2) void attn_fp16_kernel(
    const __half* __restrict__ Q, const __half* __restrict__ K,
    const __half* __restrict__ V, __half* __restrict__ O) {
  extern __shared__ __half2 sm2[];
  __half* sVh = reinterpret_cast<__half*>(sm2 + OV2);

  const int tid = threadIdx.x;
  const int warp = tid >> 5, lane = tid & 31;
  const int g = lane >> 2, t = lane & 3;
  const int rr = warp * 16;  // 4 warps x 16 rows = Br 64
  const int bh = blockIdx.y;
  const int b = bh >> 3, h = bh & 7;
  const int n0 = blockIdx.x * 64;

  const __half* Qb = Q + (size_t)b * NN * CC + (size_t)h * DH;
  const __half* Kb = K + (size_t)b * NN * CC + (size_t)h * DH;
  const __half* Vb = V + (size_t)b * NN * CC + (size_t)h * DH;
  const __half2 sc2 = __floats2half2_rn(0.08838834764831845f,
                                        0.08838834764831845f);

  const unsigned smb = (unsigned)__cvta_generic_to_shared(sm2);
  const int lrow = lane & 15, l16 = lane >> 4;
  const int bcol = (lane & 7) + 8 * ((lane >> 3) & 1);
  const unsigned qlm = smb + (rr + lrow) * (Q2_STR * 4) + l16 * 16;
  const unsigned klm = smb + OK2 * 4 + bcol * (Q2_STR * 4) + l16 * 16;
  const unsigned vlm = smb + OV2 * 4 + bcol * (V_STR * 2) + l16 * 16;

  // ---- Q tile (64 rows x 16 uint4), pre-scaled ----
#pragma unroll
  for (int i = 0; i < 8; i++) {
    int l = tid + 128 * i;
    int r = l >> 4, w = l & 15;
    uint4 v = *(const uint4*)(Qb + (size_t)(n0 + r) * CC + w * 8);
    __half2* d = sm2 + r * Q2_STR + w * 4;
    d[0] = __hmul2(*(__half2*)&v.x, sc2);
    d[1] = __hmul2(*(__half2*)&v.y, sc2);
    d[2] = __hmul2(*(__half2*)&v.z, sc2);
    d[3] = __hmul2(*(__half2*)&v.w, sc2);
  }

  float m0 = -INFINITY, m1 = -INFINITY, l0 = 0.f, l1 = 0.f;
  float oacc[16][4];
#pragma unroll
  for (int nt = 0; nt < 16; nt++)
#pragma unroll
    for (int i = 0; i < 4; i++) oacc[nt][i] = 0.f;
  __syncthreads();

  for (int j0 = 0; j0 < NN; j0 += 64) {
    // ---- K/V chunks: 64 rows x 16 uint4 each over 128 threads ----
#pragma unroll
    for (int i = 0; i < 8; i++) {
      int l = tid + 128 * i;
      int r = l >> 4, w = l & 15;
      *(uint4*)(sm2 + OK2 + r * Q2_STR + w * 4) =
          *(const uint4*)(Kb + (size_t)(j0 + r) * CC + w * 8);
      *(uint4*)(sVh + r * V_STR + w * 8) =
          *(const uint4*)(Vb + (size_t)(j0 + r) * CC + w * 8);
    }
    __syncthreads();

    // ---- S = Q @ K^T ----
    float sacc[8][4];
#pragma unroll
    for (int nt = 0; nt < 8; nt++)
#pragma unroll
      for (int i = 0; i < 4; i++) sacc[nt][i] = 0.f;

#pragma unroll
    for (int ks = 0; ks < 8; ks++) {
      unsigned a[4];
      ldsm_x4(a, qlm + ks * 32);
#pragma unroll
      for (int j = 0; j < 4; j++) {
        unsigned bb[4];
        ldsm_x4(bb, klm + j * (16 * Q2_STR * 4) + ks * 32);
        hmma16(sacc[2 * j], a, bb[0], bb[2]);
        hmma16(sacc[2 * j + 1], a, bb[1], bb[3]);
      }
    }

    // ---- register softmax ----
    float mx0 = -INFINITY, mx1 = -INFINITY;
#pragma unroll
    for (int nt = 0; nt < 8; nt++) {
      mx0 = fmaxf(mx0, fmaxf(sacc[nt][0], sacc[nt][1]));
      mx1 = fmaxf(mx1, fmaxf(sacc[nt][2], sacc[nt][3]));
    }
    mx0 = fmaxf(mx0, __shfl_xor_sync(0xffffffffu, mx0, 1));
    mx0 = fmaxf(mx0, __shfl_xor_sync(0xffffffffu, mx0, 2));
    mx1 = fmaxf(mx1, __shfl_xor_sync(0xffffffffu, mx1, 1));
    mx1 = fmaxf(mx1, __shfl_xor_sync(0xffffffffu, mx1, 2));

    const float mn0 = fmaxf(m0, mx0), mn1 = fmaxf(m1, mx1);
    const float al0 = __expf(m0 - mn0), al1 = __expf(m1 - mn1);
    m0 = mn0;
    m1 = mn1;

    __half2 pa[8], pb[8];
    float s0 = 0.f, s1 = 0.f;
#pragma unroll
    for (int nt = 0; nt < 8; nt++) {
      pa[nt] = __floats2half2_rn(__expf(sacc[nt][0] - mn0),
                                 __expf(sacc[nt][1] - mn0));
      pb[nt] = __floats2half2_rn(__expf(sacc[nt][2] - mn1),
                                 __expf(sacc[nt][3] - mn1));
      float2 fa = __half22float2(pa[nt]);
      float2 fb = __half22float2(pb[nt]);
      s0 += fa.x + fa.y;  // L from rounded P -> matches PV numerator
      s1 += fb.x + fb.y;
    }
    s0 += __shfl_xor_sync(0xffffffffu, s0, 1);
    s0 += __shfl_xor_sync(0xffffffffu, s0, 2);
    s1 += __shfl_xor_sync(0xffffffffu, s1, 1);
    s1 += __shfl_xor_sync(0xffffffffu, s1, 2);
    l0 = l0 * al0 + s0;
    l1 = l1 * al1 + s1;

#pragma unroll
    for (int nt = 0; nt < 16; nt++) {
      oacc[nt][0] *= al0;
      oacc[nt][1] *= al0;
      oacc[nt][2] *= al1;
      oacc[nt][3] *= al1;
    }

    // ---- PV: ldmatrix.trans on V ----
#pragma unroll
    for (int ks = 0; ks < 4; ks++) {
      unsigned a[4];
      a[0] = h2u(pa[2 * ks]);
      a[1] = h2u(pb[2 * ks]);
      a[2] = h2u(pa[2 * ks + 1]);
      a[3] = h2u(pb[2 * ks + 1]);
      const unsigned vK = vlm + ks * (16 * V_STR * 2);
#pragma unroll
      for (int j = 0; j < 8; j++) {
        unsigned bb[4];
        ldsm_x4t(bb, vK + j * 32);
        hmma16(oacc[2 * j], a, bb[0], bb[1]);
        hmma16(oacc[2 * j + 1], a, bb[2], bb[3]);
      }
    }
    __syncthreads();
  }

  // ---- epilogue (half out) ----
  __half* Ob = O + (size_t)b * NN * CC + (size_t)h * DH;
  const float inv0 = 1.0f / l0, inv1 = 1.0f / l1;
  const int row = n0 + rr + g;
#pragma unroll
  for (int nt = 0; nt < 16; nt++) {
    const int c = nt * 8 + 2 * t;
    *(__half2*)(Ob + (size_t)row * CC + c) =
        __floats2half2_rn(oacc[nt][0] * inv0, oacc[nt][1] * inv0);
    *(__half2*)(Ob + (size_t)(row + 8) * CC + c) =
        __floats2half2_rn(oacc[nt][2] * inv1, oacc[nt][3] * inv1);
  }
}

// ---------------------------------------------------------------------------
extern "C" void kernel_launch(void* const* d_in, const int* in_sizes, int n_in,
                              void* d_out, int out_size) {
  const float* xq = (const float*)d_in[0];
  const float* xkv = (const float*)d_in[1];
  const float* Wq = (const float*)d_in[2];
  const float* bq = (const float*)d_in[3];
  const float* Wk = (const float*)d_in[4];
  const float* bk = (const float*)d_in[5];
  const float* Wv = (const float*)d_in[6];
  const float* bv = (const float*)d_in[7];
  const float* Wo = (const float*)d_in[8];
  const float* bo = (const float*)d_in[9];
  float* out = (float*)d_out;

  __half *xqh, *xkvh, *qh, *kh, *vh, *atth, *wt;
  cudaGetSymbolAddress((void**)&xqh, g_xqh);
  cudaGetSymbolAddress((void**)&xkvh, g_xkvh);
  cudaGetSymbolAddress((void**)&qh, g_qh);
  cudaGetSymbolAddress((void**)&kh, g_kh);
  cudaGetSymbolAddress((void**)&vh, g_vh);
  cudaGetSymbolAddress((void**)&atth, g_atth);
  cudaGetSymbolAddress((void**)&wt, g_wt);

  cudaFuncSetAttribute(attn_fp16_kernel,
                       cudaFuncAttributeMaxDynamicSharedMemorySize,
                       ATT_SMEM_BYTES);
  cudaFuncSetAttribute(hgemm_cp_kernel<__half>,
                       cudaFuncAttributeMaxDynamicSharedMemorySize, GEMM_SMEM);
  cudaFuncSetAttribute(hgemm_cp_kernel<float>,
                       cudaFuncAttributeMaxDynamicSharedMemorySize, GEMM_SMEM);

  const size_t WSZ = (size_t)CC * CC;
  const int CV_BLK = (MALL * CC / 4) / 256;
  f2h_kernel<<<CV_BLK, 256>>>(xq, xqh);
  f2h_kernel<<<CV_BLK, 256>>>(xkv, xkvh);
  transpose_h_kernel<<<dim3(32, 32, 4), 256>>>(Wq, Wk, Wv, Wo, wt);

  dim3 gg(CC / 128, MALL / 128);  // (8, 32)
  hgemm_cp_kernel<__half><<<gg, 256, GEMM_SMEM>>>(xqh, wt + 0 * WSZ, bq, qh);
  hgemm_cp_kernel<__half><<<gg, 256, GEMM_SMEM>>>(xkvh, wt + 1 * WSZ, bk, kh);
  hgemm_cp_kernel<__half><<<gg, 256, GEMM_SMEM>>>(xkvh, wt + 2 * WSZ, bv, vh);
  attn_fp16_kernel<<<dim3(NN / 64, BB * HH), 128, ATT_SMEM_BYTES>>>(qh, kh,
                                                                    vh, atth);
  hgemm_cp_kernel<float><<<gg, 256, GEMM_SMEM>>>(atth, wt + 3 * WSZ, bo, out);
}